// round 11
// baseline (speedup 1.0000x reference)
#include <cuda_runtime.h>

// Spatial GCN on a 24x24 grid: adj = D^-1 A + I (4-neighbor grid) => 5-point
// stencil with analytic 1/deg(neighbor) in {1/2, 1/3, 1/4}. Then elementwise
// weight, BatchNorm2d (batch stats), LeakyReLU(0.2).
//
// R10 (resubmit after infra failure): fused one-block-per-channel. Two staging
// groups of 32 images (72 KB smem), 8 deep-prefetched LDG.128 per thread per
// group. y for all 16 images per thread stays in REGISTERS across the BN
// reduction; phase 2 is pure fma+leaky+STG from registers.

#define B_   64
#define C_   512
#define NN   576
#define BN_EPS 1e-4f
#define SLOPE  0.2f

#define TPB  576          // 18 warps; thread = (s=t/144, chunk r=t%144)

__device__ __forceinline__ float invd(int d) {
    // d in {2,3,4}
    return d == 4 ? 0.25f : (d == 3 ? (1.0f / 3.0f) : 0.5f);
}

extern __shared__ float xs[];        // 32 * 576 floats = 73728 B staging

__global__ __launch_bounds__(TPB, 1)
void k_fused(const float* __restrict__ x,
             const float* __restrict__ w,
             const float* __restrict__ gamma,
             const float* __restrict__ beta,
             float* __restrict__ out) {
    __shared__ float red1[18], red2[18];
    __shared__ float s_scale, s_shift;

    const int t = threadIdx.x;
    const int s = t / 144;                        // 0..3
    const int r = t - 144 * s;                    // chunk 0..143
    const int i = r / 6;                          // row
    const int q = r - 6 * i;                      // chunk-in-row
    const int c = blockIdx.x;                     // channel
    // thread's images: b = 4*k + s, k = 0..15. group g in {0,1}: k = 8g..8g+7,
    // covering images b in [32g, 32g+31]; smem slot = b & 31.

    // ---- stencil coefficients (chunk-position only) ----
    const int rti = (i > 0) + (i < 23);
    const int rtu = (i > 1) + 1;                  // rowterm(i-1), valid iff i>0
    const int rtd = 1 + (i < 22);                 // rowterm(i+1), valid iff i<23
    const float cHi = invd(rti + 2);
    const float cHe = invd(rti + 1);
    const float cUi = invd(rtu + 2), cUe = invd(rtu + 1);
    const float cDi = invd(rtd + 2), cDe = invd(rtd + 1);

    const bool q0 = (q == 0), q5 = (q == 5);
    const bool hasU = (i > 0), hasD = (i < 23);
    const float cL0 = q0 ? 0.0f : cHi;
    const float cL1 = q0 ? cHe  : cHi;
    const float cR2 = q5 ? cHe  : cHi;
    const float cR3 = q5 ? 0.0f : cHi;
    const float vU = hasU ? 1.0f : 0.0f;
    const float vD = hasD ? 1.0f : 0.0f;
    const float cU0 = vU * (q0 ? cUe : cUi), cUm = vU * cUi, cU3 = vU * (q5 ? cUe : cUi);
    const float cD0 = vD * (q0 ? cDe : cDi), cDm = vD * cDi, cD3 = vD * (q5 ? cDe : cDi);

    const int upOff = hasU ? -24 : 0;             // clamped (coeff 0 when clamped)
    const int dnOff = hasD ?  24 : 0;
    const int lfOff = q0 ? 0 : -1;
    const int rgOff = q5 ? 0 :  4;

    const float4 wv = __ldg((const float4*)(w + c * NN + r * 4));

    float4 y[16];                                 // all outputs live in regs
    float s1 = 0.0f, s2 = 0.0f;
    float4 buf[8];

    // prefetch group 0 (8 back-to-back LDG.128 -> MLP 8)
    #pragma unroll
    for (int j = 0; j < 8; j++) {
        const int b = 4 * j + s;
        buf[j] = *(const float4*)(x + ((size_t)b * C_ + c) * NN + r * 4);
    }

    #pragma unroll
    for (int g = 0; g < 2; g++) {
        // commit group g to smem (slot = b & 31)
        #pragma unroll
        for (int j = 0; j < 8; j++) {
            const int slot = 4 * j + s;
            *(float4*)(xs + slot * NN + r * 4) = buf[j];
        }
        __syncthreads();
        // prefetch group 1 while computing group 0
        if (g == 0) {
            #pragma unroll
            for (int j = 0; j < 8; j++) {
                const int b = 4 * (8 + j) + s;
                buf[j] = *(const float4*)(x + ((size_t)b * C_ + c) * NN + r * 4);
            }
        }
        // stencil + weight for group g, stats accumulate, y -> regs
        #pragma unroll
        for (int j = 0; j < 8; j++) {
            const int slot = 4 * j + s;
            const float* xc = xs + slot * NN + r * 4;
            const float4 c4 = *(const float4*)xc;
            const float4 up = *(const float4*)(xc + upOff);
            const float4 dn = *(const float4*)(xc + dnOff);
            const float  lf = xc[lfOff];
            const float  rg = xc[rgOff];

            const float t0 = c4.x + cL0 * lf   + cHi * c4.y + cU0 * up.x + cD0 * dn.x;
            const float t1 = c4.y + cL1 * c4.x + cHi * c4.z + cUm * up.y + cDm * dn.y;
            const float t2 = c4.z + cHi * c4.y + cR2 * c4.w + cUm * up.z + cDm * dn.z;
            const float t3 = c4.w + cHi * c4.z + cR3 * rg   + cU3 * up.w + cD3 * dn.w;

            const float y0 = t0 * wv.x, y1 = t1 * wv.y, y2 = t2 * wv.z, y3 = t3 * wv.w;
            y[8 * g + j] = make_float4(y0, y1, y2, y3);
            s1 += (y0 + y1) + (y2 + y3);
            s2 += (y0 * y0 + y1 * y1) + (y2 * y2 + y3 * y3);
        }
        if (g == 0) __syncthreads();  // all reads of group 0 done before overwrite
    }

    // ---- block reduction (deterministic) ----
    const unsigned FULL = 0xFFFFFFFFu;
    #pragma unroll
    for (int o = 16; o; o >>= 1) {
        s1 += __shfl_down_sync(FULL, s1, o);
        s2 += __shfl_down_sync(FULL, s2, o);
    }
    const int wid = t >> 5, lane = t & 31;
    if (lane == 0) { red1[wid] = s1; red2[wid] = s2; }
    __syncthreads();
    if (wid == 0) {
        float a = (lane < 18) ? red1[lane] : 0.0f;
        float b = (lane < 18) ? red2[lane] : 0.0f;
        #pragma unroll
        for (int o = 16; o; o >>= 1) {
            a += __shfl_down_sync(FULL, a, o);
            b += __shfl_down_sync(FULL, b, o);
        }
        if (lane == 0) {
            const float invn = 1.0f / 36864.0f;   // 1/(B*NN)
            const float mean = a * invn;
            const float var  = b * invn - mean * mean;
            const float sc = gamma[c] * rsqrtf(var + BN_EPS);
            s_scale = sc;
            s_shift = beta[c] - mean * sc;
        }
    }
    __syncthreads();

    const float sc = s_scale, sh = s_shift;

    // ---- phase 2: normalize + LeakyReLU straight from registers ----
    #pragma unroll
    for (int k = 0; k < 16; k++) {
        const int b = 4 * k + s;
        float n0 = fmaf(y[k].x, sc, sh);
        float n1 = fmaf(y[k].y, sc, sh);
        float n2 = fmaf(y[k].z, sc, sh);
        float n3 = fmaf(y[k].w, sc, sh);
        n0 = (n0 >= 0.f) ? n0 : SLOPE * n0;
        n1 = (n1 >= 0.f) ? n1 : SLOPE * n1;
        n2 = (n2 >= 0.f) ? n2 : SLOPE * n2;
        n3 = (n3 >= 0.f) ? n3 : SLOPE * n3;
        *(float4*)(out + ((size_t)b * C_ + c) * NN + r * 4) =
            make_float4(n0, n1, n2, n3);
    }
}

extern "C" void kernel_launch(void* const* d_in, const int* in_sizes, int n_in,
                              void* d_out, int out_size) {
    const float* x     = (const float*)d_in[0];   // [64,512,24,24]
    // d_in[1] = adj (unused: grid structure exploited analytically)
    const float* w     = (const float*)d_in[2];   // [512,576]
    const float* gamma = (const float*)d_in[3];   // [512]
    const float* beta  = (const float*)d_in[4];   // [512]
    float* out = (float*)d_out;

    const int smem = 32 * NN * (int)sizeof(float);          // 73728 B
    cudaFuncSetAttribute(k_fused, cudaFuncAttributeMaxDynamicSharedMemorySize, smem);
    k_fused<<<C_, TPB, smem>>>(x, w, gamma, beta, out);
}